// round 4
// baseline (speedup 1.0000x reference)
#include <cuda_runtime.h>
#include <cuda_fp16.h>
#include <stdint.h>

#define H     128
#define CIN   64
#define NNODE 512
#define BATCH 2

// uint32 (=half2) strides; row stride ≡ 4 banks -> 8-row LDSM phases conflict-free
#define ESTRIDE 68    // E tile: 128 rows x 64 half2 (K-major)
#define WSTRIDE 68    // WT tile: 128 n-rows x 64 kpair (K-major, transposed weights)

// smem layout (bytes)
#define OFF_ES   0
#define SZ_T     (128 * 68 * 4)                  // 34816
#define OFF_W2   (OFF_ES + SZ_T)                 // 34816
#define OFF_W3   (OFF_W2 + SZ_T)                 // 69632
#define OFF_OUTS (OFF_W3 + SZ_T)                 // 104448
#define OFF_BC2  (OFF_OUTS + 512)
#define OFF_BC3  (OFF_BC2 + 512)
#define OFF_WO   (OFF_BC3 + 512)
#define SMEM_BYTES (OFF_WO + 512)                // 106496

// scratch: u[b,n,k] = (relu-MLP h2)[b,n,:] @ Wc1
__device__ float g_U[BATCH * NNODE * H];

// ---------------------------------------------------------------------------
__device__ __forceinline__ uint32_t pack2(float a, float b) {
    __half2 h = __floats2half2_rn(a, b);
    return *reinterpret_cast<uint32_t*>(&h);
}

__device__ __forceinline__ void mma_f16(float c[4], const uint32_t a[4],
                                        uint32_t b0, uint32_t b1) {
    asm volatile(
        "mma.sync.aligned.m16n8k16.row.col.f32.f16.f16.f32 "
        "{%0,%1,%2,%3}, {%4,%5,%6,%7}, {%8,%9}, {%0,%1,%2,%3};"
        : "+f"(c[0]), "+f"(c[1]), "+f"(c[2]), "+f"(c[3])
        : "r"(a[0]), "r"(a[1]), "r"(a[2]), "r"(a[3]), "r"(b0), "r"(b1));
}

__device__ __forceinline__ void ldsm_x4(uint32_t& r0, uint32_t& r1,
                                        uint32_t& r2, uint32_t& r3,
                                        uint32_t saddr) {
    asm volatile(
        "ldmatrix.sync.aligned.m8n8.x4.shared.b16 {%0,%1,%2,%3}, [%4];"
        : "=r"(r0), "=r"(r1), "=r"(r2), "=r"(r3) : "r"(saddr));
}

// 128x128x128 fp16 GEMM via LDSM fragments.
// aA[mt]: byte smem addr for A ldmatrix at k0=0, mt tile; +32B per k-step
// aB[ntp]: byte smem addr for B ldmatrix at k0=0, ntp (=2 nt) tile
__device__ __forceinline__ void gemm128h(const uint32_t aA[2], const uint32_t aB[4],
                                         float acc[2][8][4]) {
#pragma unroll
    for (int k0 = 0; k0 < 8; k0++) {   // 16 halves per step
        uint32_t a[2][4];
#pragma unroll
        for (int mt = 0; mt < 2; mt++)
            ldsm_x4(a[mt][0], a[mt][1], a[mt][2], a[mt][3], aA[mt] + k0 * 32);
#pragma unroll
        for (int ntp = 0; ntp < 4; ntp++) {
            uint32_t b00, b01, b10, b11;   // b0/b1 for nt=2ntp and 2ntp+1
            ldsm_x4(b00, b01, b10, b11, aB[ntp] + k0 * 32);
            mma_f16(acc[0][2 * ntp],     a[0], b00, b01);
            mma_f16(acc[1][2 * ntp],     a[1], b00, b01);
            mma_f16(acc[0][2 * ntp + 1], a[0], b10, b11);
            mma_f16(acc[1][2 * ntp + 1], a[1], b10, b11);
        }
    }
}

// ---------------------------------------------------------------------------
// stage 1: node MLP + u = h2 @ Wc1   (fp32 exact, tiny)
// ---------------------------------------------------------------------------
#define S1_NODES 8
__global__ __launch_bounds__(128) void stage1_kernel(
    const float* __restrict__ x,
    const float* __restrict__ Wa, const float* __restrict__ ba,
    const float* __restrict__ Wb, const float* __restrict__ bb,
    const float* __restrict__ Wc1) {
    __shared__ float xs[S1_NODES][CIN];
    __shared__ float h1s[S1_NODES][H + 4];
    __shared__ float h2s[S1_NODES][H + 4];
    int tid = threadIdx.x;
    int node0 = blockIdx.x * S1_NODES;

    for (int idx = tid; idx < S1_NODES * CIN; idx += 128)
        xs[idx / CIN][idx % CIN] = x[node0 * CIN + idx];
    __syncthreads();

    int k = tid;
    float acc[S1_NODES];
#pragma unroll
    for (int m = 0; m < S1_NODES; m++) acc[m] = ba[k];
#pragma unroll 8
    for (int c = 0; c < CIN; c++) {
        float w = Wa[c * H + k];
#pragma unroll
        for (int m = 0; m < S1_NODES; m++) acc[m] += xs[m][c] * w;
    }
#pragma unroll
    for (int m = 0; m < S1_NODES; m++) h1s[m][k] = fmaxf(acc[m], 0.f);
    __syncthreads();

#pragma unroll
    for (int m = 0; m < S1_NODES; m++) acc[m] = bb[k];
#pragma unroll 8
    for (int c = 0; c < H; c++) {
        float w = Wb[c * H + k];
#pragma unroll
        for (int m = 0; m < S1_NODES; m++) acc[m] += h1s[m][c] * w;
    }
#pragma unroll
    for (int m = 0; m < S1_NODES; m++) h2s[m][k] = fmaxf(acc[m], 0.f);
    __syncthreads();

#pragma unroll
    for (int m = 0; m < S1_NODES; m++) acc[m] = 0.f;
#pragma unroll 8
    for (int c = 0; c < H; c++) {
        float w = Wc1[c * H + k];
#pragma unroll
        for (int m = 0; m < S1_NODES; m++) acc[m] += h2s[m][c] * w;
    }
#pragma unroll
    for (int m = 0; m < S1_NODES; m++) g_U[(node0 + m) * H + k] = acc[m];
}

// ---------------------------------------------------------------------------
// stage 2: per-edge MLP via fp16 mma + LDSM, 2 CTAs / SM
// ---------------------------------------------------------------------------
__global__ __launch_bounds__(256, 2) void stage2_kernel(
    const float* __restrict__ bc1,
    const float* __restrict__ Wc2, const float* __restrict__ bc2,
    const float* __restrict__ Wc3, const float* __restrict__ bc3,
    const float* __restrict__ Wo, const float* __restrict__ bo,
    float* __restrict__ out, int ntiles) {
    extern __shared__ unsigned char smem[];
    uint32_t* Es  = (uint32_t*)(smem + OFF_ES);
    uint32_t* W2T = (uint32_t*)(smem + OFF_W2);
    uint32_t* W3T = (uint32_t*)(smem + OFF_W3);
    float* outs = (float*)(smem + OFF_OUTS);
    float* bc2s = (float*)(smem + OFF_BC2);
    float* bc3s = (float*)(smem + OFF_BC3);
    float* wos  = (float*)(smem + OFF_WO);

    int tid = threadIdx.x;

    // one-time: stage weights TRANSPOSED as half2, K-major rows:
    //   WT[n][kp] = (W[2kp][n], W[2kp+1][n])
    for (int idx = tid; idx < H * 64; idx += 256) {
        int n = idx >> 6, kp = idx & 63;
        W2T[n * WSTRIDE + kp] = pack2(Wc2[(2 * kp) * H + n], Wc2[(2 * kp + 1) * H + n]);
        W3T[n * WSTRIDE + kp] = pack2(Wc3[(2 * kp) * H + n], Wc3[(2 * kp + 1) * H + n]);
    }
    if (tid < H) {
        bc2s[tid] = bc2[tid];
        bc3s[tid] = bc3[tid];
        wos[tid]  = Wo[tid];
    }
    float bo_v = bo[0];

    int c2 = tid & 63;            // half2 column owned in E1 fill
    int r0 = tid >> 6;            // row phase (0..3)
    float2 bc1v = ((const float2*)bc1)[c2];
    __syncthreads();

    int warp = tid >> 5, lane = tid & 31;
    int wm = warp >> 1, wn = warp & 1;
    int m_base = wm * 32, n_base = wn * 64;
    int qid = lane >> 2, tq = lane & 3;

    // ldmatrix per-lane base addresses (byte smem addrs at k0=0)
    uint32_t es_s  = (uint32_t)__cvta_generic_to_shared(Es);
    uint32_t w2_s  = (uint32_t)__cvta_generic_to_shared(W2T);
    uint32_t w3_s  = (uint32_t)__cvta_generic_to_shared(W3T);
    // A: lanes 0-7 rows m0..m0+7 @k0 | 8-15 rows +8 @k0 | 16-23 rows m0.. @k0+4 | 24-31 rows +8 @k0+4
    int a_row = (lane & 7) + ((lane >> 3) & 1) * 8;
    int a_c4  = (lane >> 4) * 4;
    uint32_t aA[2];
#pragma unroll
    for (int mt = 0; mt < 2; mt++)
        aA[mt] = es_s + ((m_base + mt * 16 + a_row) * ESTRIDE + a_c4) * 4;
    // B: lanes 0-7 n0..n0+7 @k0 | 8-15 n0..+7 @k0+4 | 16-23 n0+8.. @k0 | 24-31 n0+8.. @k0+4
    int b_row = (lane & 7) + ((lane >> 4) & 1) * 8;
    int b_c4  = ((lane >> 3) & 1) * 4;
    uint32_t aB2[4], aB3[4];
#pragma unroll
    for (int ntp = 0; ntp < 4; ntp++) {
        uint32_t off = ((n_base + ntp * 16 + b_row) * WSTRIDE + b_c4) * 4;
        aB2[ntp] = w2_s + off;
        aB3[ntp] = w3_s + off;
    }

    for (int t = blockIdx.x; t < ntiles; t += gridDim.x) {
        int jt = t & 3;
        int i  = (t >> 2) & (NNODE - 1);
        int b  = t >> 11;
        int j0 = jt << 7;
        const float2* Ub2 = (const float2*)(g_U + (size_t)b * NNODE * H);
        float2 ui = Ub2[i * 64 + c2];

        // E1[j,k] = ReLU(u[j,k] - u[i,k] + bc1[k]) -> half2 in smem
#pragma unroll 8
        for (int it = 0; it < 32; it++) {
            int jj = r0 + 4 * it;
            float2 uv = Ub2[(j0 + jj) * 64 + c2];
            Es[jj * ESTRIDE + c2] = pack2(fmaxf(uv.x - ui.x + bc1v.x, 0.f),
                                          fmaxf(uv.y - ui.y + bc1v.y, 0.f));
        }
        __syncthreads();

        // GEMM1: Z2 = E1 @ Wc2
        float acc[2][8][4];
#pragma unroll
        for (int mt = 0; mt < 2; mt++)
#pragma unroll
            for (int nt = 0; nt < 8; nt++)
#pragma unroll
                for (int q = 0; q < 4; q++) acc[mt][nt][q] = 0.f;
        gemm128h(aA, aB2, acc);
        __syncthreads();  // all reads of E1 done

        // E2 = ReLU(Z2 + bc2) -> half2 back into Es
#pragma unroll
        for (int mt = 0; mt < 2; mt++) {
            int r = m_base + mt * 16 + qid;
#pragma unroll
            for (int nt = 0; nt < 8; nt++) {
                int n  = n_base + nt * 8 + 2 * tq;
                int np = n >> 1;
                Es[r * ESTRIDE + np] =
                    pack2(fmaxf(acc[mt][nt][0] + bc2s[n], 0.f),
                          fmaxf(acc[mt][nt][1] + bc2s[n + 1], 0.f));
                Es[(r + 8) * ESTRIDE + np] =
                    pack2(fmaxf(acc[mt][nt][2] + bc2s[n], 0.f),
                          fmaxf(acc[mt][nt][3] + bc2s[n + 1], 0.f));
            }
        }
        if (tid < H) outs[tid] = bo_v;
        __syncthreads();

        // GEMM2: Z3 = E2 @ Wc3
#pragma unroll
        for (int mt = 0; mt < 2; mt++)
#pragma unroll
            for (int nt = 0; nt < 8; nt++)
#pragma unroll
                for (int q = 0; q < 4; q++) acc[mt][nt][q] = 0.f;
        gemm128h(aA, aB3, acc);

        // epilogue: out_row += sum_n ReLU(Z3 + bc3) * Wo
#pragma unroll
        for (int mt = 0; mt < 2; mt++) {
            float s0 = 0.f, s1 = 0.f;
#pragma unroll
            for (int nt = 0; nt < 8; nt++) {
                int n = n_base + nt * 8 + 2 * tq;
                s0 += fmaxf(acc[mt][nt][0] + bc3s[n], 0.f) * wos[n]
                    + fmaxf(acc[mt][nt][1] + bc3s[n + 1], 0.f) * wos[n + 1];
                s1 += fmaxf(acc[mt][nt][2] + bc3s[n], 0.f) * wos[n]
                    + fmaxf(acc[mt][nt][3] + bc3s[n + 1], 0.f) * wos[n + 1];
            }
            s0 += __shfl_xor_sync(0xffffffffu, s0, 1);
            s0 += __shfl_xor_sync(0xffffffffu, s0, 2);
            s1 += __shfl_xor_sync(0xffffffffu, s1, 1);
            s1 += __shfl_xor_sync(0xffffffffu, s1, 2);
            if (tq == 0) {
                atomicAdd(&outs[m_base + mt * 16 + qid], s0);
                atomicAdd(&outs[m_base + mt * 16 + qid + 8], s1);
            }
        }
        __syncthreads();

        if (tid < H)
            out[((size_t)b * NNODE + i) * NNODE + j0 + tid] = outs[tid];
        __syncthreads();
    }
}

// ---------------------------------------------------------------------------
extern "C" void kernel_launch(void* const* d_in, const int* in_sizes, int n_in,
                              void* d_out, int out_size) {
    const float* x   = (const float*)d_in[0];
    const float* Wa  = (const float*)d_in[1];
    const float* ba  = (const float*)d_in[2];
    const float* Wb  = (const float*)d_in[3];
    const float* bb  = (const float*)d_in[4];
    const float* Wc1 = (const float*)d_in[5];
    const float* bc1 = (const float*)d_in[6];
    const float* Wc2 = (const float*)d_in[7];
    const float* bc2 = (const float*)d_in[8];
    const float* Wc3 = (const float*)d_in[9];
    const float* bc3 = (const float*)d_in[10];
    const float* Wo  = (const float*)d_in[11];
    const float* bo  = (const float*)d_in[12];
    float* out = (float*)d_out;

    cudaFuncSetAttribute(stage2_kernel,
                         cudaFuncAttributeMaxDynamicSharedMemorySize, SMEM_BYTES);

    stage1_kernel<<<(BATCH * NNODE) / S1_NODES, 128>>>(x, Wa, ba, Wb, bb, Wc1);

    int ntiles = BATCH * NNODE * (NNODE / 128);  // 4096
    stage2_kernel<<<304, 256, SMEM_BYTES>>>(bc1, Wc2, bc2, Wc3, bc3, Wo, bo,
                                            out, ntiles);
}

// round 6
// speedup vs baseline: 2.3631x; 2.3631x over previous
// NOTE (pitfall, recorded R4): harness PTX target is sm_103 (no 'a'), so
// tcgen05/TMEM instructions do not compile. Legacy mma.sync is the only
// tensor path for this bench.
#include <cuda_runtime.h>
#include <cuda_fp16.h>
#include <stdint.h>

#define H     128
#define CIN   64
#define NNODE 512
#define BATCH 2

// uint32 (=half2) strides, conflict-free per-fragment (validated R2)
#define ESTRIDE 68    // E tile: 128 rows x 64 half2
#define WSTRIDE 136   // W tile: 64 kpair-rows x 128 n

// smem layout (bytes)
#define OFF_ES   0
#define SZ_ES    (128 * ESTRIDE * 4)             // 34816
#define OFF_W2   (OFF_ES + SZ_ES)                // 34816
#define SZ_W     (64 * WSTRIDE * 4)              // 34816
#define OFF_W3   (OFF_W2 + SZ_W)                 // 69632
#define OFF_BC2  (OFF_W3 + SZ_W)                 // 104448
#define OFF_BC3  (OFF_BC2 + 512)
#define OFF_WO   (OFF_BC3 + 512)
#define SMEM_BYTES (OFF_WO + 512)                // 105984

// scratch: u[b,n,k] = (relu-MLP h2)[b,n,:] @ Wc1
__device__ float g_U[BATCH * NNODE * H];

// ---------------------------------------------------------------------------
__device__ __forceinline__ uint32_t pack2(float a, float b) {
    __half2 h = __floats2half2_rn(a, b);
    return *reinterpret_cast<uint32_t*>(&h);
}

__device__ __forceinline__ void mma_f16(float c[4], const uint32_t a[4],
                                        uint32_t b0, uint32_t b1) {
    asm volatile(
        "mma.sync.aligned.m16n8k16.row.col.f32.f16.f16.f32 "
        "{%0,%1,%2,%3}, {%4,%5,%6,%7}, {%8,%9}, {%0,%1,%2,%3};"
        : "+f"(c[0]), "+f"(c[1]), "+f"(c[2]), "+f"(c[3])
        : "r"(a[0]), "r"(a[1]), "r"(a[2]), "r"(a[3]), "r"(b0), "r"(b1));
}

// 128x128x128 fp16 GEMM: acc += Es(128x128 half) @ Ws(128x128 half)
__device__ __forceinline__ void gemm128h(const uint32_t* __restrict__ Es,
                                         const uint32_t* __restrict__ Ws,
                                         float acc[2][8][4],
                                         int m_base, int n_base, int qid, int tq) {
#pragma unroll
    for (int k0 = 0; k0 < 64; k0 += 8) {   // k0 in half2 units (16 halves/step)
        uint32_t a[2][4];
#pragma unroll
        for (int mt = 0; mt < 2; mt++) {
            const uint32_t* er = Es + (m_base + mt * 16 + qid) * ESTRIDE + k0 + tq;
            a[mt][0] = er[0];
            a[mt][1] = er[8 * ESTRIDE];
            a[mt][2] = er[4];
            a[mt][3] = er[8 * ESTRIDE + 4];
        }
        const uint32_t* wr = Ws + (k0 + tq) * WSTRIDE + n_base + qid;
#pragma unroll
        for (int nt = 0; nt < 8; nt++) {
            uint32_t b0 = wr[nt * 8];
            uint32_t b1 = wr[4 * WSTRIDE + nt * 8];
            mma_f16(acc[0][nt], a[0], b0, b1);
            mma_f16(acc[1][nt], a[1], b0, b1);
        }
    }
}

// ---------------------------------------------------------------------------
// init: out[...] = bo   (lets stage2 epilogue use RED.GLOBAL.ADD directly)
// ---------------------------------------------------------------------------
__global__ __launch_bounds__(256) void init_out_kernel(float* __restrict__ out,
                                                       const float* __restrict__ bo) {
    float v = bo[0];
    float4 vv = make_float4(v, v, v, v);
    int i = blockIdx.x * blockDim.x + threadIdx.x;
    ((float4*)out)[2 * i]     = vv;
    ((float4*)out)[2 * i + 1] = vv;
}

// ---------------------------------------------------------------------------
// stage 1: node MLP + u = h2 @ Wc1   (fp32 exact, tiny)
// ---------------------------------------------------------------------------
#define S1_NODES 4
__global__ __launch_bounds__(128) void stage1_kernel(
    const float* __restrict__ x,
    const float* __restrict__ Wa, const float* __restrict__ ba,
    const float* __restrict__ Wb, const float* __restrict__ bb,
    const float* __restrict__ Wc1) {
    __shared__ float xs[S1_NODES][CIN];
    __shared__ float h1s[S1_NODES][H + 4];
    __shared__ float h2s[S1_NODES][H + 4];
    int tid = threadIdx.x;
    int node0 = blockIdx.x * S1_NODES;

    for (int idx = tid; idx < S1_NODES * CIN; idx += 128)
        xs[idx / CIN][idx % CIN] = x[node0 * CIN + idx];
    __syncthreads();

    int k = tid;
    float acc[S1_NODES];
#pragma unroll
    for (int m = 0; m < S1_NODES; m++) acc[m] = ba[k];
#pragma unroll 8
    for (int c = 0; c < CIN; c++) {
        float w = Wa[c * H + k];
#pragma unroll
        for (int m = 0; m < S1_NODES; m++) acc[m] += xs[m][c] * w;
    }
#pragma unroll
    for (int m = 0; m < S1_NODES; m++) h1s[m][k] = fmaxf(acc[m], 0.f);
    __syncthreads();

#pragma unroll
    for (int m = 0; m < S1_NODES; m++) acc[m] = bb[k];
#pragma unroll 8
    for (int c = 0; c < H; c++) {
        float w = Wb[c * H + k];
#pragma unroll
        for (int m = 0; m < S1_NODES; m++) acc[m] += h1s[m][c] * w;
    }
#pragma unroll
    for (int m = 0; m < S1_NODES; m++) h2s[m][k] = fmaxf(acc[m], 0.f);
    __syncthreads();

#pragma unroll
    for (int m = 0; m < S1_NODES; m++) acc[m] = 0.f;
#pragma unroll 8
    for (int c = 0; c < H; c++) {
        float w = Wc1[c * H + k];
#pragma unroll
        for (int m = 0; m < S1_NODES; m++) acc[m] += h2s[m][c] * w;
    }
#pragma unroll
    for (int m = 0; m < S1_NODES; m++) g_U[(node0 + m) * H + k] = acc[m];
}

// ---------------------------------------------------------------------------
// stage 2: per-edge MLP via fp16 mma (fp32 accum), 2 CTAs / SM, 4 syncs/tile
// ---------------------------------------------------------------------------
__global__ __launch_bounds__(256, 2) void stage2_kernel(
    const float* __restrict__ bc1,
    const float* __restrict__ Wc2, const float* __restrict__ bc2,
    const float* __restrict__ Wc3, const float* __restrict__ bc3,
    const float* __restrict__ Wo,
    float* __restrict__ out, int ntiles) {
    extern __shared__ unsigned char smem[];
    uint32_t* Es  = (uint32_t*)(smem + OFF_ES);
    uint32_t* W2s = (uint32_t*)(smem + OFF_W2);
    uint32_t* W3s = (uint32_t*)(smem + OFF_W3);
    float* bc2s = (float*)(smem + OFF_BC2);
    float* bc3s = (float*)(smem + OFF_BC3);
    float* wos  = (float*)(smem + OFF_WO);

    int tid = threadIdx.x;

    // one-time: stage weights as half2 (k-pair packed)
    for (int idx = tid; idx < 64 * H; idx += 256) {
        int kp = idx >> 7, n = idx & 127;
        W2s[kp * WSTRIDE + n] = pack2(Wc2[(2 * kp) * H + n], Wc2[(2 * kp + 1) * H + n]);
        W3s[kp * WSTRIDE + n] = pack2(Wc3[(2 * kp) * H + n], Wc3[(2 * kp + 1) * H + n]);
    }
    if (tid < H) {
        bc2s[tid] = bc2[tid];
        bc3s[tid] = bc3[tid];
        wos[tid]  = Wo[tid];
    }

    // fill mapping: thread owns 4 float cols (cg) x 16 rows (phase rph)
    int cg  = tid & 31;           // float4 column group (cols 4cg..4cg+3)
    int rph = tid >> 5;           // row phase 0..7
    float4 bc1v = ((const float4*)bc1)[cg];
    __syncthreads();

    int warp = tid >> 5, lane = tid & 31;
    int wm = warp >> 1, wn = warp & 1;
    int m_base = wm * 32, n_base = wn * 64;
    int qid = lane >> 2, tq = lane & 3;

    for (int t = blockIdx.x; t < ntiles; t += gridDim.x) {
        int jt = t & 3;
        int i  = (t >> 2) & (NNODE - 1);
        int b  = t >> 11;
        int j0 = jt << 7;
        const float4* Ub4 = (const float4*)(g_U + (size_t)b * NNODE * H);

        // vcomb = bc1 - u_i (this thread's 4 columns)
        float4 ui = Ub4[i * 32 + cg];
        float4 vc = make_float4(bc1v.x - ui.x, bc1v.y - ui.y,
                                bc1v.z - ui.z, bc1v.w - ui.w);

        // E1[j,k] = ReLU(u_j + vc) -> half2 in smem (16 rows per thread)
#pragma unroll 4
        for (int it = 0; it < 16; it++) {
            int jj = rph + 8 * it;
            float4 u = Ub4[(size_t)(j0 + jj) * 32 + cg];
            uint32_t p0 = pack2(fmaxf(u.x + vc.x, 0.f), fmaxf(u.y + vc.y, 0.f));
            uint32_t p1 = pack2(fmaxf(u.z + vc.z, 0.f), fmaxf(u.w + vc.w, 0.f));
            ((uint2*)(Es + jj * ESTRIDE))[cg] = make_uint2(p0, p1);
        }
        __syncthreads();  // (A) E1 ready

        // GEMM1: Z2 = E1 @ Wc2
        float acc[2][8][4];
#pragma unroll
        for (int mt = 0; mt < 2; mt++)
#pragma unroll
            for (int nt = 0; nt < 8; nt++)
#pragma unroll
                for (int q = 0; q < 4; q++) acc[mt][nt][q] = 0.f;
        gemm128h(Es, W2s, acc, m_base, n_base, qid, tq);
        __syncthreads();  // (B) E1 reads done

        // E2 = ReLU(Z2 + bc2) -> half2 back into Es
#pragma unroll
        for (int mt = 0; mt < 2; mt++) {
            int r = m_base + mt * 16 + qid;
#pragma unroll
            for (int nt = 0; nt < 8; nt++) {
                int n  = n_base + nt * 8 + 2 * tq;
                int np = n >> 1;
                Es[r * ESTRIDE + np] =
                    pack2(fmaxf(acc[mt][nt][0] + bc2s[n], 0.f),
                          fmaxf(acc[mt][nt][1] + bc2s[n + 1], 0.f));
                Es[(r + 8) * ESTRIDE + np] =
                    pack2(fmaxf(acc[mt][nt][2] + bc2s[n], 0.f),
                          fmaxf(acc[mt][nt][3] + bc2s[n + 1], 0.f));
            }
        }
        __syncthreads();  // (C) E2 ready

        // GEMM2: Z3 = E2 @ Wc3
#pragma unroll
        for (int mt = 0; mt < 2; mt++)
#pragma unroll
            for (int nt = 0; nt < 8; nt++)
#pragma unroll
                for (int q = 0; q < 4; q++) acc[mt][nt][q] = 0.f;
        gemm128h(Es, W3s, acc, m_base, n_base, qid, tq);
        __syncthreads();  // (D) E2 reads done -> next fill may overwrite

        // epilogue: out[b,i,j0+row] += sum_n ReLU(Z3 + bc3) * Wo  (RED.GLOBAL)
        float* orow = out + ((size_t)b * NNODE + i) * NNODE + j0;
#pragma unroll
        for (int mt = 0; mt < 2; mt++) {
            float s0 = 0.f, s1 = 0.f;
#pragma unroll
            for (int nt = 0; nt < 8; nt++) {
                int n = n_base + nt * 8 + 2 * tq;
                s0 += fmaxf(acc[mt][nt][0] + bc3s[n], 0.f) * wos[n]
                    + fmaxf(acc[mt][nt][1] + bc3s[n + 1], 0.f) * wos[n + 1];
                s1 += fmaxf(acc[mt][nt][2] + bc3s[n], 0.f) * wos[n]
                    + fmaxf(acc[mt][nt][3] + bc3s[n + 1], 0.f) * wos[n + 1];
            }
            s0 += __shfl_xor_sync(0xffffffffu, s0, 1);
            s0 += __shfl_xor_sync(0xffffffffu, s0, 2);
            s1 += __shfl_xor_sync(0xffffffffu, s1, 1);
            s1 += __shfl_xor_sync(0xffffffffu, s1, 2);
            if (tq == 0) {
                atomicAdd(orow + m_base + mt * 16 + qid, s0);
                atomicAdd(orow + m_base + mt * 16 + qid + 8, s1);
            }
        }
    }
}

// ---------------------------------------------------------------------------
extern "C" void kernel_launch(void* const* d_in, const int* in_sizes, int n_in,
                              void* d_out, int out_size) {
    const float* x   = (const float*)d_in[0];
    const float* Wa  = (const float*)d_in[1];
    const float* ba  = (const float*)d_in[2];
    const float* Wb  = (const float*)d_in[3];
    const float* bb  = (const float*)d_in[4];
    const float* Wc1 = (const float*)d_in[5];
    const float* bc1 = (const float*)d_in[6];
    const float* Wc2 = (const float*)d_in[7];
    const float* bc2 = (const float*)d_in[8];
    const float* Wc3 = (const float*)d_in[9];
    const float* bc3 = (const float*)d_in[10];
    const float* Wo  = (const float*)d_in[11];
    const float* bo  = (const float*)d_in[12];
    float* out = (float*)d_out;

    cudaFuncSetAttribute(stage2_kernel,
                         cudaFuncAttributeMaxDynamicSharedMemorySize, SMEM_BYTES);

    // out = bo everywhere (524288 floats = 131072 float4, 2 per thread)
    init_out_kernel<<<256, 256>>>(out, bo);
    stage1_kernel<<<(BATCH * NNODE) / S1_NODES, 128>>>(x, Wa, ba, Wb, bb, Wc1);

    int ntiles = BATCH * NNODE * (NNODE / 128);  // 4096
    stage2_kernel<<<304, 256, SMEM_BYTES>>>(bc1, Wc2, bc2, Wc3, bc3, Wo,
                                            out, ntiles);
}